// round 4
// baseline (speedup 1.0000x reference)
#include <cuda_runtime.h>
#include <math_constants.h>

static constexpr int   N_ATOMS = 256;
static constexpr float RCUT    = 6.0f;
static constexpr float RCUT2   = 36.0f;
static constexpr int   NFEAT   = 24;

// packed f32x2 helpers (Blackwell fma.rn.f32x2)
__device__ __forceinline__ unsigned long long pk2(float lo, float hi) {
    unsigned long long d;
    asm("mov.b64 %0, {%1, %2};" : "=l"(d)
        : "r"(__float_as_uint(lo)), "r"(__float_as_uint(hi)));
    return d;
}
__device__ __forceinline__ void upk2(unsigned long long v, float& lo, float& hi) {
    unsigned int a, b;
    asm("mov.b64 {%0, %1}, %2;" : "=r"(a), "=r"(b) : "l"(v));
    lo = __uint_as_float(a); hi = __uint_as_float(b);
}
__device__ __forceinline__ unsigned long long ffma2(unsigned long long a,
                                                    unsigned long long b,
                                                    unsigned long long c) {
    unsigned long long d;
    asm("fma.rn.f32x2 %0, %1, %2, %3;" : "=l"(d) : "l"(a), "l"(b), "l"(c));
    return d;
}

__global__ __launch_bounds__(256, 4)
void acsf_kernel(const float* __restrict__ zn,
                 const float* __restrict__ coords,
                 float* __restrict__ out)
{
    const int i    = blockIdx.x;
    const int b    = blockIdx.y;
    const int tid  = threadIdx.x;
    const int lane = tid & 31;
    const int wid  = tid >> 5;

    __shared__ float4 sA[N_ATOMS];       // dx, dy, dz, sq
    __shared__ float4 sB[N_ATOMS];       // fc, e01, e10, rinv
    __shared__ float  radw[7][8];
    __shared__ float  angw[16][8];
    __shared__ int    wcnt[8], woff[8];
    __shared__ int    sM;

    const float* cb = coords + (size_t)b * N_ATOMS * 3;
    const float xi = cb[3*i+0], yi = cb[3*i+1], zi = cb[3*i+2];

    // ---- Phase 1: pair (i, j=tid): radial features + per-neighbor factors ----
    const int   j  = tid;
    const float dx = xi - cb[3*j+0];
    const float dy = yi - cb[3*j+1];
    const float dz = zi - cb[3*j+2];
    const float sq = dx*dx + dy*dy + dz*dz;
    const bool  valid = (j != i) && (sq < RCUT2);
    const float r  = sqrtf(sq);
    const float fc = valid ? 0.5f * (__cosf(CUDART_PI_F * r * (1.0f/RCUT)) + 1.0f)
                           : 0.0f;

    float g[7];
    {
        const float rm2 = r - 2.0f;
        g[0] = fc;
        g[1] = __expf(-0.1f * sq        ) * fc;   // (rs=0, eta=0.1)
        g[2] = __expf(-1.0f * sq        ) * fc;   // (rs=0, eta=1.0)
        g[3] = __expf(-0.1f * rm2 * rm2 ) * fc;   // (rs=2, eta=0.1)
        g[4] = __expf(-1.0f * rm2 * rm2 ) * fc;   // (rs=2, eta=1.0)
        g[5] = __cosf(1.0f * r) * fc;             // kappa=1
        g[6] = __cosf(2.0f * r) * fc;             // kappa=2
    }
#pragma unroll
    for (int f = 0; f < 7; f++) {
        float v = g[f];
#pragma unroll
        for (int s = 16; s > 0; s >>= 1) v += __shfl_down_sync(0xffffffffu, v, s);
        if (lane == 0) radw[f][wid] = v;
    }

    // ---- Phase 2: deterministic neighbor compaction (ascending j) ----
    const unsigned bm = __ballot_sync(0xffffffffu, valid);
    const int before = __popc(bm & ((1u << lane) - 1u));
    if (lane == 0) wcnt[wid] = __popc(bm);
    __syncthreads();
    if (tid == 0) {
        int o = 0;
#pragma unroll
        for (int w = 0; w < 8; w++) { woff[w] = o; o += wcnt[w]; }
        sM = o;
    }
    __syncthreads();
    if (valid) {
        const int p = woff[wid] + before;
        sA[p] = make_float4(dx, dy, dz, sq);
        sB[p] = make_float4(fc,
                            __expf(-0.01f * sq),   // e01 (eta=0.01 half-factor)
                            __expf(-0.1f  * sq),   // e10 (eta=0.1 half-factor)
                            rsqrtf(sq));           // 1/r
    }
    __syncthreads();

    const int M = sM;

    // ---- Phase 3: angular sums. Warp owns rows k, lanes stride j<k. ----
    // Accumulators packed as (e3-part, e2-part) f32x2.
    unsigned long long acc[8];
#pragma unroll
    for (int f = 0; f < 8; f++) acc[f] = 0ull;

    // fc(s) = 0.5*(cos(pi*sqrt(s)/6)+1); cos as deg-8 Taylor in v = pi^2 s/36
    const float C1 = -0.5f;
    const float C2 =  1.0f / 24.0f;
    const float C3 = -1.0f / 720.0f;
    const float C4 =  1.0f / 40320.0f;
    const float C5 = -1.0f / 3628800.0f;
    const float C6 =  1.0f / 479001600.0f;
    const float C7 = -1.0f / 87178291200.0f;
    const float C8 =  1.0f / 20922789888000.0f;
    const float VSC = CUDART_PI_F * CUDART_PI_F / 36.0f;

    for (int k = 1 + wid; k < M; k += 8) {
        const float4 ak = sA[k];   // broadcast
        const float4 bk = sB[k];
        for (int jj = lane; jj < k; jj += 32) {
            const float4 aj = sA[jj];
            const float4 bj = sB[jj];

            const float dot  = aj.x*ak.x + aj.y*ak.y + aj.z*ak.z;
            const float c    = dot * bj.w * bk.w;            // cos(theta)
            const float sq2  = aj.w + ak.w;
            const float sqjk = fmaf(-2.0f, dot, sq2);        // |dj-dk|^2

            // fc(r_jk) via polynomial in sqjk
            const float v  = sqjk * VSC;
            float cs = fmaf(C8, v, C7);
            cs = fmaf(cs, v, C6);  cs = fmaf(cs, v, C5);
            cs = fmaf(cs, v, C4);  cs = fmaf(cs, v, C3);
            cs = fmaf(cs, v, C2);  cs = fmaf(cs, v, C1);
            cs = fmaf(cs, v, 1.0f);
            const float fcjk = (sqjk < RCUT2) ? 0.5f * (cs + 1.0f) : 0.0f;

            const float w2  = bj.x * bk.x;                   // fcj*fck
            const float e2a = bj.y * bk.y * w2;              // exp(-.01 sq2)*w2
            const float e2b = bj.z * bk.z * w2;              // exp(-.1  sq2)*w2

            const float t   = __expf(-0.01f * sqjk);
            const float t2  = t * t, t4 = t2 * t2;
            const float t10 = t4 * t4 * t2;                  // exp(-.1 sqjk)

            const float e3a = e2a * (t   * fcjk);
            const float e3b = e2b * (t10 * fcjk);

            const float p  = fmaxf(1.0f + c, 0.0f);
            const float m  = fmaxf(1.0f - c, 0.0f);
            const float p2 = p*p, p4 = p2*p2;
            const float m2 = m*m, m4 = m2*m2;

            const unsigned long long Ea = pk2(e3a, e2a);
            const unsigned long long Eb = pk2(e3b, e2b);
            const unsigned long long Mv = pk2(m,  m );
            const unsigned long long Pv = pk2(p,  p );
            const unsigned long long M4 = pk2(m4, m4);
            const unsigned long long P4 = pk2(p4, p4);

            acc[0] = ffma2(Mv, Ea, acc[0]);
            acc[1] = ffma2(Pv, Ea, acc[1]);
            acc[2] = ffma2(M4, Ea, acc[2]);
            acc[3] = ffma2(P4, Ea, acc[3]);
            acc[4] = ffma2(Mv, Eb, acc[4]);
            acc[5] = ffma2(Pv, Eb, acc[5]);
            acc[6] = ffma2(M4, Eb, acc[6]);
            acc[7] = ffma2(P4, Eb, acc[7]);
        }
    }

#pragma unroll
    for (int f = 0; f < 8; f++) {
        float v3, v2;
        upk2(acc[f], v3, v2);
#pragma unroll
        for (int s = 16; s > 0; s >>= 1) {
            v3 += __shfl_down_sync(0xffffffffu, v3, s);
            v2 += __shfl_down_sync(0xffffffffu, v2, s);
        }
        if (lane == 0) { angw[f][wid] = v3; angw[8 + f][wid] = v2; }
    }
    __syncthreads();

    // ---- Output: 24 features, fixed summation order ----
    if (tid == 0) {
        float* o = out + ((size_t)(b * N_ATOMS + i)) * NFEAT;
        o[0] = zn[i];
#pragma unroll
        for (int f = 0; f < 7; f++) {
            float s = 0.0f;
#pragma unroll
            for (int w = 0; w < 8; w++) s += radw[f][w];
            o[1 + f] = s;
        }
        // x2 (j<k symmetry) * 2^(1-zeta): zeta=1 -> 2, zeta=4 -> 0.25
        const float sc[8] = {2.0f, 2.0f, 0.25f, 0.25f, 2.0f, 2.0f, 0.25f, 0.25f};
#pragma unroll
        for (int f = 0; f < 8; f++) {
            float s3 = 0.0f, s2 = 0.0f;
#pragma unroll
            for (int w = 0; w < 8; w++) { s3 += angw[f][w]; s2 += angw[8 + f][w]; }
            o[8  + f] = s3 * sc[f];
            o[16 + f] = s2 * sc[f];
        }
    }
}

extern "C" void kernel_launch(void* const* d_in, const int* in_sizes, int n_in,
                              void* d_out, int out_size)
{
    const float* zn     = (const float*)d_in[0];   // atomic_numbers [N]
    const float* coords = (const float*)d_in[1];   // coordinates   [B, N, 3]
    float*       out    = (float*)d_out;           // [B, N, 24]

    const int B = in_sizes[1] / (N_ATOMS * 3);
    dim3 grid(N_ATOMS, B);
    acsf_kernel<<<grid, 256>>>(zn, coords, out);
}

// round 5
// speedup vs baseline: 1.5333x; 1.5333x over previous
#include <cuda_runtime.h>
#include <math_constants.h>

static constexpr int   N_ATOMS = 256;
static constexpr float RCUT    = 6.0f;
static constexpr float RCUT2   = 36.0f;
static constexpr int   NFEAT   = 24;

// packed f32x2 helpers (Blackwell fma.rn.f32x2)
__device__ __forceinline__ unsigned long long pk2(float lo, float hi) {
    unsigned long long d;
    asm("mov.b64 %0, {%1, %2};" : "=l"(d)
        : "r"(__float_as_uint(lo)), "r"(__float_as_uint(hi)));
    return d;
}
__device__ __forceinline__ void upk2(unsigned long long v, float& lo, float& hi) {
    unsigned int a, b;
    asm("mov.b64 {%0, %1}, %2;" : "=r"(a), "=r"(b) : "l"(v));
    lo = __uint_as_float(a); hi = __uint_as_float(b);
}
__device__ __forceinline__ unsigned long long ffma2(unsigned long long a,
                                                    unsigned long long b,
                                                    unsigned long long c) {
    unsigned long long d;
    asm("fma.rn.f32x2 %0, %1, %2, %3;" : "=l"(d) : "l"(a), "l"(b), "l"(c));
    return d;
}

__global__ __launch_bounds__(256, 4)
void acsf_kernel(const float* __restrict__ zn,
                 const float* __restrict__ coords,
                 float* __restrict__ out)
{
    const int i    = blockIdx.x;
    const int b    = blockIdx.y;
    const int tid  = threadIdx.x;
    const int lane = tid & 31;
    const int wid  = tid >> 5;

    __shared__ float4 sA[N_ATOMS];     // dx, dy, dz, sq
    __shared__ float4 sB[N_ATOMS];     // u1 = fc*e^{-.01 sq}, u2 = fc*e^{-.1 sq}, rinv, fc
    __shared__ float  radw[7][8];
    __shared__ float  angw[16][8];
    __shared__ int    wcnt[8], woff[8];
    __shared__ int    sM;

    const float* cb = coords + (size_t)b * N_ATOMS * 3;
    const float xi = cb[3*i+0], yi = cb[3*i+1], zi = cb[3*i+2];

    // ---- Phase 1: pair (i, j=tid): radial features + per-neighbor factors ----
    const int   j  = tid;
    const float dx = xi - cb[3*j+0];
    const float dy = yi - cb[3*j+1];
    const float dz = zi - cb[3*j+2];
    const float sq = dx*dx + dy*dy + dz*dz;
    const bool  valid = (j != i) && (sq < RCUT2);
    const float r  = sqrtf(sq);
    const float fc = valid ? 0.5f * (__cosf(CUDART_PI_F * r * (1.0f/RCUT)) + 1.0f)
                           : 0.0f;

    float g[7];
    {
        const float rm2 = r - 2.0f;
        g[0] = fc;
        g[1] = __expf(-0.1f * sq        ) * fc;   // (rs=0, eta=0.1)
        g[2] = __expf(-1.0f * sq        ) * fc;   // (rs=0, eta=1.0)
        g[3] = __expf(-0.1f * rm2 * rm2 ) * fc;   // (rs=2, eta=0.1)
        g[4] = __expf(-1.0f * rm2 * rm2 ) * fc;   // (rs=2, eta=1.0)
        g[5] = __cosf(1.0f * r) * fc;             // kappa=1
        g[6] = __cosf(2.0f * r) * fc;             // kappa=2
    }
#pragma unroll
    for (int f = 0; f < 7; f++) {
        float v = g[f];
#pragma unroll
        for (int s = 16; s > 0; s >>= 1) v += __shfl_down_sync(0xffffffffu, v, s);
        if (lane == 0) radw[f][wid] = v;
    }

    // ---- Phase 2: deterministic neighbor compaction (ascending j) ----
    const unsigned bm = __ballot_sync(0xffffffffu, valid);
    const int before = __popc(bm & ((1u << lane) - 1u));
    if (lane == 0) wcnt[wid] = __popc(bm);
    __syncthreads();
    if (tid == 0) {
        int o = 0;
#pragma unroll
        for (int w = 0; w < 8; w++) { woff[w] = o; o += wcnt[w]; }
        sM = o;
    }
    __syncthreads();
    if (valid) {
        const int p = woff[wid] + before;
        sA[p] = make_float4(dx, dy, dz, sq);
        const float e01 = __expf(-0.01f * sq);
        const float e10 = __expf(-0.1f  * sq);
        sB[p] = make_float4(fc * e01, fc * e10, rsqrtf(sq), fc);
    }
    __syncthreads();

    const int M      = sM;
    const int npairs = M * (M - 1) / 2;

    // ---- Phase 3: balanced flat pair loop, lanes take consecutive idx ----
    unsigned long long acc[8];
#pragma unroll
    for (int f = 0; f < 8; f++) acc[f] = 0ull;

    // fc(s) = 0.5*(cos(pi*sqrt(s)/6)+1) = fma(0.5*v, poly(v), 1), v = pi^2 s/36
    const float C1 = -0.5f;
    const float C2 =  1.0f / 24.0f;
    const float C3 = -1.0f / 720.0f;
    const float C4 =  1.0f / 40320.0f;
    const float C5 = -1.0f / 3628800.0f;
    const float C6 =  1.0f / 479001600.0f;
    const float C7 = -1.0f / 87178291200.0f;
    const float C8 =  1.0f / 20922789888000.0f;
    const float VSC = CUDART_PI_F * CUDART_PI_F / 36.0f;

    for (int idx = tid; idx < npairs; idx += 256) {
        // triangular decode: idx = k*(k-1)/2 + jj, 0 <= jj < k < M
        int k = (int)((sqrtf(8.0f * (float)idx + 1.0f) + 1.0f) * 0.5f);
        while (k * (k - 1) / 2 > idx)  k--;
        while ((k + 1) * k / 2 <= idx) k++;
        const int jj = idx - k * (k - 1) / 2;

        const float4 aj = sA[jj];
        const float4 ak = sA[k];
        const float4 bj = sB[jj];
        const float4 bk = sB[k];

        const float dot  = aj.x*ak.x + aj.y*ak.y + aj.z*ak.z;
        const float c    = dot * bj.z * bk.z;            // cos(theta)
        const float sq2  = aj.w + ak.w;
        const float sqjk = fmaf(-2.0f, dot, sq2);        // |dj-dk|^2 (law of cosines)

        // fc(r_jk): even polynomial in sqjk (no sqrt, no cos)
        const float v  = sqjk * VSC;
        float poly = fmaf(C8, v, C7);
        poly = fmaf(poly, v, C6);  poly = fmaf(poly, v, C5);
        poly = fmaf(poly, v, C4);  poly = fmaf(poly, v, C3);
        poly = fmaf(poly, v, C2);  poly = fmaf(poly, v, C1);
        float fcjk = fmaf(0.5f * v, poly, 1.0f);
        fcjk = (sqjk < RCUT2) ? fcjk : 0.0f;

        const float e2a = bj.x * bk.x;                   // e^{-.01(sqj+sqk)} fcj fck
        const float e2b = bj.y * bk.y;                   // e^{-.1 (sqj+sqk)} fcj fck

        const float t   = __expf(-0.01f * sqjk);
        const float t2  = t * t, t4 = t2 * t2;
        const float t10 = t4 * t4 * t2;                  // e^{-.1 sqjk}

        const float e3a = e2a * (t   * fcjk);
        const float e3b = e2b * (t10 * fcjk);

        const float p  = fmaxf(1.0f + c, 0.0f);
        const float m  = fmaxf(1.0f - c, 0.0f);
        const float p2 = p*p, p4 = p2*p2;
        const float m2 = m*m, m4 = m2*m2;

        const unsigned long long Ea = pk2(e3a, e2a);
        const unsigned long long Eb = pk2(e3b, e2b);
        const unsigned long long Mv = pk2(m,  m );
        const unsigned long long Pv = pk2(p,  p );
        const unsigned long long M4 = pk2(m4, m4);
        const unsigned long long P4 = pk2(p4, p4);

        acc[0] = ffma2(Mv, Ea, acc[0]);
        acc[1] = ffma2(Pv, Ea, acc[1]);
        acc[2] = ffma2(M4, Ea, acc[2]);
        acc[3] = ffma2(P4, Ea, acc[3]);
        acc[4] = ffma2(Mv, Eb, acc[4]);
        acc[5] = ffma2(Pv, Eb, acc[5]);
        acc[6] = ffma2(M4, Eb, acc[6]);
        acc[7] = ffma2(P4, Eb, acc[7]);
    }

#pragma unroll
    for (int f = 0; f < 8; f++) {
        float v3, v2;
        upk2(acc[f], v3, v2);
#pragma unroll
        for (int s = 16; s > 0; s >>= 1) {
            v3 += __shfl_down_sync(0xffffffffu, v3, s);
            v2 += __shfl_down_sync(0xffffffffu, v2, s);
        }
        if (lane == 0) { angw[f][wid] = v3; angw[8 + f][wid] = v2; }
    }
    __syncthreads();

    // ---- Output: 24 features, fixed summation order ----
    if (tid == 0) {
        float* o = out + ((size_t)(b * N_ATOMS + i)) * NFEAT;
        o[0] = zn[i];
#pragma unroll
        for (int f = 0; f < 7; f++) {
            float s = 0.0f;
#pragma unroll
            for (int w = 0; w < 8; w++) s += radw[f][w];
            o[1 + f] = s;
        }
        // x2 (j<k symmetry) * 2^(1-zeta): zeta=1 -> 2, zeta=4 -> 0.25
        const float sc[8] = {2.0f, 2.0f, 0.25f, 0.25f, 2.0f, 2.0f, 0.25f, 0.25f};
#pragma unroll
        for (int f = 0; f < 8; f++) {
            float s3 = 0.0f, s2 = 0.0f;
#pragma unroll
            for (int w = 0; w < 8; w++) { s3 += angw[f][w]; s2 += angw[8 + f][w]; }
            o[8  + f] = s3 * sc[f];
            o[16 + f] = s2 * sc[f];
        }
    }
}

extern "C" void kernel_launch(void* const* d_in, const int* in_sizes, int n_in,
                              void* d_out, int out_size)
{
    const float* zn     = (const float*)d_in[0];   // atomic_numbers [N]
    const float* coords = (const float*)d_in[1];   // coordinates   [B, N, 3]
    float*       out    = (float*)d_out;           // [B, N, 24]

    const int B = in_sizes[1] / (N_ATOMS * 3);
    dim3 grid(N_ATOMS, B);
    acsf_kernel<<<grid, 256>>>(zn, coords, out);
}